// round 10
// baseline (speedup 1.0000x reference)
#include <cuda_runtime.h>
#include <math.h>

#define NN 3000
#define EE 48000
#define K1 1500
#define K2 750
#define KWP 384      // padded packed-word K dim (1500/4=375 -> 384)
#define NP2 768      // padded K2 for packed operands
#define GRID 148     // <= SM count (GB300 has 152) -> all blocks co-resident
#define TPB 256

// ---------------- device memory pools ----------------
// Z region zeroed in-kernel (phase 0)
static const size_t Z_A1   = 0;                      // 1500*1500
static const size_t Z_AGG1 = Z_A1   + 2250000;       // 1500*64
static const size_t Z_AGG2 = Z_AGG1 + 96000;         // 750*64
static const size_t Z_AGG3 = Z_AGG2 + 48000;         // 1500*64
static const size_t Z_DEG1 = Z_AGG3 + 96000;         // 1504
static const size_t Z_DEG2 = Z_DEG1 + 1504;          // 752
static const size_t ZTOT   = Z_DEG2 + 752;           // 2492256 (mult of 4)
static const size_t F_A2   = ZTOT;                   // 750*750
static const size_t F_XW   = F_A2   + 562500;
static const size_t F_XS   = F_XW   + 192000;
static const size_t F_H0   = F_XS   + 192000;
static const size_t F_H1   = F_H0   + 192000;
static const size_t F_H2   = F_H1   + 96000;
static const size_t F_HUP  = F_H2   + 48000;
static const size_t F_SC   = F_HUP  + 96000;
static const size_t F_TOT  = F_SC   + 3008;

__device__ float g_fpool[F_TOT];

static const size_t IZ_CNT     = 0;                  // 3000
static const size_t IZ_COLCNT  = 3000;
static const size_t IZ_FILL    = 6000;
static const size_t IZ_COLFILL = 9000;
static const size_t IZTOT      = 12000;              // zeroed in-kernel (mult of 4)
static const size_t I_ROWPTR = 12000;                // 3004
static const size_t I_COLPTR = I_ROWPTR + 3004;
static const size_t I_COLS   = I_COLPTR + 3004;
static const size_t I_CSRC   = I_COLS   + 48000;
static const size_t I_PERM1  = I_CSRC   + 48000;
static const size_t I_PERM2  = I_PERM1  + 1504;
static const size_t I_MAP1   = I_PERM2  + 768;
static const size_t I_MAP2   = I_MAP1   + 3000;
static const size_t I_APT    = I_MAP2   + 1504;
static const size_t I_GPT    = I_APT    + (size_t)KWP * NP2;
static const size_t I_TOT    = I_GPT    + (size_t)KWP * NP2;

__device__ int g_ipool[I_TOT];
__device__ int g_bar[64];   // phase barrier counters, memset to 0 each launch

// ---------------- device helpers ----------------

__device__ __forceinline__ void gbar(int p) {
    __syncthreads();
    if (threadIdx.x == 0) {
        __threadfence();
        atomicAdd(&g_bar[p], 1);
        while (((volatile int*)g_bar)[p] < GRID) { }
        __threadfence();
    }
    __syncthreads();
}

__device__ __forceinline__ unsigned f2o(float f) {
    unsigned b = __float_as_uint(f);
    return (b & 0x80000000u) ? ~b : (b | 0x80000000u);
}

// block-0 only: two exclusive scans (256 threads, 12 elems each)
__device__ void phase_scan(char* shm, const int* cnt, int* rowptr,
                           const int* colcnt, int* colptr) {
    int* part = (int*)shm;
    int tid = threadIdx.x;
    for (int rep = 0; rep < 2; rep++) {
        const int* src = rep ? colcnt : cnt;
        int* dst = rep ? colptr : rowptr;
        int base = tid * 12;
        int loc[12]; int sum = 0;
        #pragma unroll
        for (int q = 0; q < 12; q++) { loc[q] = sum; int v = (base + q < NN) ? src[base + q] : 0; sum += v; }
        part[tid] = sum;
        __syncthreads();
        for (int off = 1; off < TPB; off <<= 1) {
            int t = (tid >= off) ? part[tid - off] : 0;
            __syncthreads();
            part[tid] += t;
            __syncthreads();
        }
        int offset = tid ? part[tid - 1] : 0;
        #pragma unroll
        for (int q = 0; q < 12; q++) if (base + q < NN) dst[base + q] = offset + loc[q];
        if (tid == TPB - 1) dst[NN] = part[TPB - 1];
        __syncthreads();
    }
}

// block-0 only: radix top-k set selection (ties at threshold -> lowest index)
__device__ void phase_select(char* shm, const float* score, int n, int k,
                             int* perm, int* map) {
    int* hist = (int*)shm;
    int* eqidx = hist + 256;
    unsigned* uscal = (unsigned*)(eqidx + 3072);   // [0]=prefix
    int* iscal = (int*)(uscal + 1);                // [0]=rem [1]=eqn [2]=poscnt
    int tid = threadIdx.x;
    if (tid == 0) { uscal[0] = 0; iscal[0] = k; iscal[1] = 0; iscal[2] = 0; }
    __syncthreads();
    for (int shift = 24; shift >= 0; shift -= 8) {
        for (int d = tid; d < 256; d += TPB) hist[d] = 0;
        __syncthreads();
        unsigned pref = uscal[0];
        unsigned hmask = (shift < 24) ? (0xFFFFFFFFu << (shift + 8)) : 0u;
        for (int i = tid; i < n; i += TPB) {
            unsigned u = f2o(score[i]);
            if ((u & hmask) == (pref & hmask)) atomicAdd(&hist[(u >> shift) & 0xFF], 1);
        }
        __syncthreads();
        if (tid == 0) {
            int rem = iscal[0], cum = 0, d = 255;
            for (; d > 0; d--) { if (cum + hist[d] >= rem) break; cum += hist[d]; }
            uscal[0] = pref | ((unsigned)d << shift);
            iscal[0] = rem - cum;
        }
        __syncthreads();
    }
    unsigned T = uscal[0];
    int rem = iscal[0];
    for (int i = tid; i < n; i += TPB) {
        unsigned u = f2o(score[i]);
        if (u > T) { int pos = atomicAdd(&iscal[2], 1); perm[pos] = i; map[i] = pos; }
        else { map[i] = -1; if (u == T) { int e = atomicAdd(&iscal[1], 1); eqidx[e] = i; } }
    }
    __syncthreads();
    int m = iscal[1];
    for (int e = tid; e < m; e += TPB) {
        int id = eqidx[e]; int rank = 0;
        for (int f = 0; f < m; f++) rank += (eqidx[f] < id);
        if (rank < rem) { int pos = atomicAdd(&iscal[2], 1); perm[pos] = id; map[id] = pos; }
    }
}

// lin64 (pooled or up-residual variant), block-strided over 4-row groups
__device__ void phase_lin64(char* shm, const float* H, const float* sc,
                            const int* permOrMap, const float* W, const float* deg,
                            float* XW, float* XS, int n, int pooled, const float* res) {
    float* sh = (float*)shm;   // 4*64
    int tid = threadIdx.x;
    int r = tid >> 6, kc = tid & 63;
    for (int base = blockIdx.x * 4; base < n; base += GRID * 4) {
        __syncthreads();
        int i = base + r;
        float lv = 0.f;
        if (i < n) {
            if (pooled) { int src = permOrMap[i]; lv = H[(size_t)src * 64 + kc] * sc[src]; }
            else { int m = permOrMap[i]; lv = res[(size_t)i * 64 + kc] + (m >= 0 ? H[(size_t)m * 64 + kc] : 0.f); }
        }
        sh[r * 64 + kc] = lv;
        __syncthreads();
        if (i < n) {
            float acc = 0.f;
            #pragma unroll
            for (int k = 0; k < 64; k++) acc += sh[r * 64 + k] * W[k * 64 + kc];
            float di = rsqrtf(deg[i] + 2.f);
            XW[i * 64 + kc] = acc;
            XS[i * 64 + kc] = acc * di;
        }
    }
}

// finalize (C=64) + optional fused score, block-strided over 4-row groups
__device__ void phase_fin(char* shm, const float* agg, const float* xw,
                          const float* deg, const float* b, float* out, int n,
                          int act, const float* p, float* score) {
    float* part = (float*)shm; float* ppart = part + 8;
    int tid = threadIdx.x;
    int r = tid >> 6, c = tid & 63;
    for (int base = blockIdx.x * 4; base < n; base += GRID * 4) {
        __syncthreads();
        int i = base + r;
        float v = 0.f;
        if (i < n) {
            float di = rsqrtf(deg[i] + 2.f);
            int idx = i * 64 + c;
            v = di * agg[idx] + 2.f * di * di * xw[idx] + b[c];
            if (act) v = tanhf(v);
            out[idx] = v;
        }
        if (p) {
            float pc = p[c];
            float hp = (i < n) ? v * pc : 0.f;
            float pp = (r == 0) ? pc * pc : 0.f;
            #pragma unroll
            for (int off = 16; off > 0; off >>= 1) {
                hp += __shfl_down_sync(0xffffffffu, hp, off);
                pp += __shfl_down_sync(0xffffffffu, pp, off);
            }
            int w = tid >> 5, lane = tid & 31;
            if (lane == 0) { part[w] = hp; ppart[w] = pp; }
            __syncthreads();
            if (tid < 4) {
                int ii = base + tid;
                if (ii < n) {
                    float dot = part[tid * 2] + part[tid * 2 + 1];
                    float pn = ppart[0] + ppart[1];
                    score[ii] = tanhf(dot * rsqrtf(pn));
                }
            }
        }
    }
}

// out[t,c] += sum_s A[s,t]*X[s,c] (dense A, 64 cols); grid-stride over (tile,chunk)
__device__ void phase_atx(char* shm, const float* A, const float* X, float* out,
                          int n, int nchunks) {
    float* As = (float*)shm;       // 8*32
    float* Xs = As + 8 * 32;       // 8*64
    int tid = threadIdx.x;
    int c = tid & 63, g = tid >> 6;
    int ntiles = (n + 31) / 32;
    int per = (n + nchunks - 1) / nchunks;
    int total = ntiles * nchunks;
    for (int b = blockIdx.x; b < total; b += GRID) {
        int tile = b % ntiles, chunk = b / ntiles;
        int T0 = tile * 32;
        int s_begin = chunk * per;
        int s_end = min(s_begin + per, n);
        float acc[8] = {0.f, 0.f, 0.f, 0.f, 0.f, 0.f, 0.f, 0.f};
        for (int s0 = s_begin; s0 < s_end; s0 += 8) {
            __syncthreads();
            { int ss = tid >> 5, tt = tid & 31;
              int gs = s0 + ss, gt = T0 + tt;
              As[ss * 32 + tt] = (gs < s_end && gt < n) ? A[(size_t)gs * n + gt] : 0.f; }
            #pragma unroll
            for (int q = 0; q < 2; q++) {
                int li = tid + q * 256;
                int ss = li >> 6, cc = li & 63;
                int gs = s0 + ss;
                Xs[ss * 64 + cc] = (gs < s_end) ? X[(size_t)gs * 64 + cc] : 0.f;
            }
            __syncthreads();
            #pragma unroll
            for (int ss = 0; ss < 8; ss++) {
                float xv = Xs[ss * 64 + c];
                #pragma unroll
                for (int k = 0; k < 8; k++) acc[k] += As[ss * 32 + g * 8 + k] * xv;
            }
        }
        #pragma unroll
        for (int k = 0; k < 8; k++) {
            int t = T0 + g * 8 + k;
            if (t < n) atomicAdd(&out[(size_t)t * 64 + c], acc[k]);
        }
    }
}

// dp4a A2 GEMM: grid-stride over 12x12 tiles
__device__ void phase_dp4a(char* shm, const int* Apt, const int* Gpt,
                           const float* A1v, const int* perm, float* A2, float* deg2) {
    int* As = (int*)shm;        // 8*68
    int* Bs = As + 544;         // 8*68
    int* prs = Bs + 544;        // 64
    int* pcs = prs + 64;        // 64
    float* csum = (float*)(pcs + 64);   // 64
    int tid = threadIdx.x;
    int tx = tid & 15, ty = tid >> 4;
    for (int b = blockIdx.x; b < 144; b += GRID) {
        int row0 = (b / 12) * 64, col0 = (b % 12) * 64;
        __syncthreads();
        if (tid < 64) { prs[tid] = (row0 + tid < K2) ? perm[row0 + tid] : 0; csum[tid] = 0.f; }
        else if (tid < 128) { int c = tid - 64; pcs[c] = (col0 + c < K2) ? perm[col0 + c] : 0; }
        __syncthreads();
        int acc[4][4] = {};
        for (int k0 = 0; k0 < KWP; k0 += 8) {
            #pragma unroll
            for (int p = 0; p < 2; p++) {
                int li = tid + p * 256;
                int w = li >> 6, c = li & 63;
                As[w * 68 + c] = Apt[(k0 + w) * NP2 + row0 + c];
                Bs[w * 68 + c] = Gpt[(k0 + w) * NP2 + col0 + c];
            }
            __syncthreads();
            #pragma unroll
            for (int kk = 0; kk < 8; kk++) {
                int4 a4 = *reinterpret_cast<const int4*>(&As[kk * 68 + ty * 4]);
                int4 b4 = *reinterpret_cast<const int4*>(&Bs[kk * 68 + tx * 4]);
                int a[4] = {a4.x, a4.y, a4.z, a4.w};
                int bb[4] = {b4.x, b4.y, b4.z, b4.w};
                #pragma unroll
                for (int i = 0; i < 4; i++)
                    #pragma unroll
                    for (int j = 0; j < 4; j++)
                        acc[i][j] = __dp4a(a[i], bb[j], acc[i][j]);
            }
            __syncthreads();
        }
        float cj[4] = {0.f, 0.f, 0.f, 0.f};
        #pragma unroll
        for (int i2 = 0; i2 < 4; i2++) {
            int gr = row0 + ty * 4 + i2;
            if (gr >= K2) continue;
            int ar = prs[ty * 4 + i2];
            #pragma unroll
            for (int j = 0; j < 4; j++) {
                int gc = col0 + tx * 4 + j;
                if (gc >= K2) continue;
                float val = (gr == gc) ? 0.f
                          : (float)acc[i2][j] + 2.f * A1v[(size_t)ar * K1 + pcs[tx * 4 + j]];
                A2[(size_t)gr * K2 + gc] = val;
                cj[j] += val;
            }
        }
        #pragma unroll
        for (int j = 0; j < 4; j++) atomicAdd(&csum[tx * 4 + j], cj[j]);
        __syncthreads();
        if (tid < 64 && col0 + tid < K2) atomicAdd(&deg2[col0 + tid], csum[tid]);
    }
}

// ---------------- the persistent mega-kernel ----------------

__global__ void __launch_bounds__(TPB, 1)
mega(const float* __restrict__ x, const int* __restrict__ ei,
     const float* __restrict__ W0, const float* __restrict__ b0,
     const float* __restrict__ W1, const float* __restrict__ b1,
     const float* __restrict__ W2, const float* __restrict__ b2,
     const float* __restrict__ p1, const float* __restrict__ p2,
     const float* __restrict__ Wu0, const float* __restrict__ bu0,
     const float* __restrict__ Wu1, const float* __restrict__ bu1,
     float* __restrict__ out) {
    __shared__ __align__(16) char shm[14336];
    float* fp = g_fpool;
    int* ip = g_ipool;
    float *A1 = fp + Z_A1, *AGG1 = fp + Z_AGG1, *AGG2 = fp + Z_AGG2,
          *AGG3 = fp + Z_AGG3, *DEG1 = fp + Z_DEG1, *DEG2 = fp + Z_DEG2,
          *A2 = fp + F_A2, *XW = fp + F_XW, *XS = fp + F_XS,
          *H0 = fp + F_H0, *H1 = fp + F_H1, *H2 = fp + F_H2, *HUP = fp + F_HUP,
          *SC = fp + F_SC;
    int *CNT = ip + IZ_CNT, *COLCNT = ip + IZ_COLCNT, *FILL = ip + IZ_FILL,
        *COLFILL = ip + IZ_COLFILL, *ROWPTR = ip + I_ROWPTR, *COLPTR = ip + I_COLPTR,
        *COLS = ip + I_COLS, *CSRC = ip + I_CSRC, *PERM1 = ip + I_PERM1,
        *PERM2 = ip + I_PERM2, *MAP1 = ip + I_MAP1, *MAP2 = ip + I_MAP2,
        *APT = ip + I_APT, *GPT = ip + I_GPT;

    int tid = threadIdx.x, bid = blockIdx.x;
    int gt = bid * TPB + tid;

    // P0: zero Z region (floats) and IZ region (ints)
    {
        float4 zf = {0.f, 0.f, 0.f, 0.f};
        int nz4 = (int)(ZTOT / 4);
        for (int i = gt; i < nz4; i += GRID * TPB) reinterpret_cast<float4*>(fp)[i] = zf;
        int4 zi = {0, 0, 0, 0};
        for (int i = gt; i < (int)(IZTOT / 4); i += GRID * TPB) reinterpret_cast<int4*>(ip)[i] = zi;
    }
    gbar(0);

    // P1: degree count
    for (int e = gt; e < EE; e += GRID * TPB) {
        atomicAdd(&CNT[ei[e]], 1);
        atomicAdd(&COLCNT[ei[EE + e]], 1);
    }
    gbar(1);

    // P2: block 0 -> scans; blocks 1..147 -> lin0 (XW = x@W0, XS scaled)
    if (bid == 0) {
        phase_scan(shm, CNT, ROWPTR, COLCNT, COLPTR);
    } else {
        float* sh = (float*)shm;   // 4*16
        int r = tid >> 6, c = tid & 63;
        for (int base = (bid - 1) * 4; base < NN; base += (GRID - 1) * 4) {
            __syncthreads();
            if (tid < 64) {
                int rr = tid >> 4, k = tid & 15;
                int i = base + rr;
                sh[rr * 16 + k] = (i < NN) ? x[i * 16 + k] : 0.f;
            }
            __syncthreads();
            int i = base + r;
            if (i < NN) {
                float acc = 0.f;
                #pragma unroll
                for (int k = 0; k < 16; k++) acc += sh[r * 16 + k] * W0[k * 64 + c];
                float di = rsqrtf((float)COLCNT[i] + 2.f);
                XW[i * 64 + c] = acc;
                XS[i * 64 + c] = acc * di;
            }
        }
    }
    gbar(2);

    // P3: fill CSR + CSC
    for (int e = gt; e < EE; e += GRID * TPB) {
        int s = ei[e], t = ei[EE + e];
        int p = ROWPTR[s] + atomicAdd(&FILL[s], 1);
        COLS[p] = t;
        int q = COLPTR[t] + atomicAdd(&COLFILL[t], 1);
        CSRC[q] = s;
    }
    gbar(3);

    // P4: GCN0 (CSC gather) + tanh + fused score1
    {
        float* part = (float*)shm; float* ppart = part + 8;
        int r = tid >> 6, c = tid & 63;
        for (int base = bid * 4; base < NN; base += GRID * 4) {
            __syncthreads();
            int i = base + r;
            float v = 0.f;
            if (i < NN) {
                float acc = 0.f;
                int q0 = COLPTR[i], q1 = COLPTR[i + 1];
                for (int q = q0; q < q1; q++) acc += XS[CSRC[q] * 64 + c];
                float di = rsqrtf((float)COLCNT[i] + 2.f);
                v = tanhf(di * acc + 2.f * di * di * XW[i * 64 + c] + b0[c]);
                H0[i * 64 + c] = v;
            }
            float pc = p1[c];
            float hp = (i < NN) ? v * pc : 0.f;
            float pp = (r == 0) ? pc * pc : 0.f;
            #pragma unroll
            for (int off = 16; off > 0; off >>= 1) {
                hp += __shfl_down_sync(0xffffffffu, hp, off);
                pp += __shfl_down_sync(0xffffffffu, pp, off);
            }
            int w = tid >> 5, lane = tid & 31;
            if (lane == 0) { part[w] = hp; ppart[w] = pp; }
            __syncthreads();
            if (tid < 4) {
                int ii = base + tid;
                if (ii < NN) {
                    float dot = part[tid * 2] + part[tid * 2 + 1];
                    float pn = ppart[0] + ppart[1];
                    SC[ii] = tanhf(dot * rsqrtf(pn));
                }
            }
        }
    }
    gbar(4);

    // P5: select1 (block 0)
    if (bid == 0) phase_select(shm, SC, NN, K1, PERM1, MAP1);
    gbar(5);

    // P6: A1 = (B@B + 2B)[perm1 x perm1] off-diag + DEG1
    for (int e = gt; e < EE; e += GRID * TPB) {
        int s = ei[e], t = ei[EE + e];
        if (s == t) continue;
        int i = MAP1[s];
        if (i < 0) continue;
        int j0 = MAP1[t];
        if (j0 >= 0 && j0 != i) {
            atomicAdd(&A1[(size_t)i * K1 + j0], 2.0f);
            atomicAdd(&DEG1[j0], 2.0f);
        }
        int q0 = ROWPTR[t], q1 = ROWPTR[t + 1];
        for (int q = q0; q < q1; q++) {
            int u = COLS[q];
            if (u == t) continue;
            int j = MAP1[u];
            if (j < 0 || j == i) continue;
            atomicAdd(&A1[(size_t)i * K1 + j], 1.0f);
            atomicAdd(&DEG1[j], 1.0f);
        }
    }
    gbar(6);

    // P7: linpool1
    phase_lin64(shm, H0, SC, PERM1, W1, DEG1, XW, XS, K1, 1, nullptr);
    gbar(7);

    // P8: AGG1 = A1^T @ XS
    phase_atx(shm, A1, XS, AGG1, K1, 3);
    gbar(8);

    // P9: finalize GCN1 + score2
    phase_fin(shm, AGG1, XW, DEG1, b1, H1, K1, 1, p2, SC);
    gbar(9);

    // P10: select2 (block 0)
    if (bid == 0) phase_select(shm, SC, K1, K2, PERM2, MAP2);
    gbar(10);

    // P11: pack int8 operands of the A2 GEMM
    {
        const int half = KWP * NP2;
        for (int idx = gt; idx < 2 * half; idx += GRID * TPB) {
            int sel = (idx >= half) ? 1 : 0;
            int l = idx - sel * half;
            int w = l / NP2, i = l - w * NP2;
            int v = 0;
            if (i < K2) {
                int pi = PERM2[i];
                if (sel == 0) {
                    const float* row = A1 + (size_t)pi * K1;
                    #pragma unroll
                    for (int q = 0; q < 4; q++) {
                        int kq = 4 * w + q;
                        int bb = (kq < K1) ? (int)row[kq] : 0;
                        v |= (bb & 0xFF) << (8 * q);
                    }
                } else {
                    #pragma unroll
                    for (int q = 0; q < 4; q++) {
                        int kq = 4 * w + q;
                        int bb = (kq < K1) ? (int)A1[(size_t)kq * K1 + pi] : 0;
                        v |= (bb & 0xFF) << (8 * q);
                    }
                }
            }
            if (sel == 0) APT[w * NP2 + i] = v; else GPT[w * NP2 + i] = v;
        }
    }
    gbar(11);

    // P12: A2 via dp4a GEMM + DEG2
    phase_dp4a(shm, APT, GPT, A1, PERM2, A2, DEG2);
    gbar(12);

    // P13: linpool2
    phase_lin64(shm, H1, SC, PERM2, W2, DEG2, XW, XS, K2, 1, nullptr);
    gbar(13);

    // P14: AGG2 = A2^T @ XS
    phase_atx(shm, A2, XS, AGG2, K2, 6);
    gbar(14);

    // P15: finalize GCN2 -> H2
    phase_fin(shm, AGG2, XW, DEG2, b2, H2, K2, 1, nullptr, nullptr);
    gbar(15);

    // P16: linup64 (res1 + scatter-back of H2)
    phase_lin64(shm, H2, nullptr, MAP2, Wu0, DEG1, XW, XS, K1, 0, H1);
    gbar(16);

    // P17: AGG3 = A1^T @ XS
    phase_atx(shm, A1, XS, AGG3, K1, 3);
    gbar(17);

    // P18: finalize up-GCN -> HUP
    phase_fin(shm, AGG3, XW, DEG1, bu0, HUP, K1, 1, nullptr, nullptr);
    gbar(18);

    // P19: linup16 (H0 + scatter-back of HUP) @ Wu1 -> 16-wide XW/XS
    {
        float* sh = (float*)shm;  // 16*64
        for (int base = bid * 16; base < NN; base += GRID * 16) {
            __syncthreads();
            #pragma unroll
            for (int q = 0; q < 4; q++) {
                int li = tid + q * 256;
                int r = li >> 6, k = li & 63;
                int i = base + r;
                float lv = 0.f;
                if (i < NN) {
                    int m = MAP1[i];
                    lv = H0[(size_t)i * 64 + k] + (m >= 0 ? HUP[(size_t)m * 64 + k] : 0.f);
                }
                sh[r * 64 + k] = lv;
            }
            __syncthreads();
            int r = tid >> 4, c = tid & 15;
            int i = base + r;
            if (i < NN) {
                float acc = 0.f;
                #pragma unroll
                for (int k = 0; k < 64; k++) acc += sh[r * 64 + k] * Wu1[k * 16 + c];
                float di = rsqrtf((float)COLCNT[i] + 2.f);
                XW[i * 16 + c] = acc;
                XS[i * 16 + c] = acc * di;
            }
        }
    }
    gbar(19);

    // P20: final GCN (CSC gather, C=16, no activation) -> out
    {
        int r = tid >> 4, c = tid & 15;
        for (int base = bid * 16; base < NN; base += GRID * 16) {
            int i = base + r;
            if (i >= NN) continue;
            float acc = 0.f;
            int q0 = COLPTR[i], q1 = COLPTR[i + 1];
            for (int q = q0; q < q1; q++) acc += XS[CSRC[q] * 16 + c];
            float di = rsqrtf((float)COLCNT[i] + 2.f);
            out[i * 16 + c] = di * acc + 2.f * di * di * XW[i * 16 + c] + bu1[c];
        }
    }
}

// ---------------- host ----------------

extern "C" void kernel_launch(void* const* d_in, const int* in_sizes, int n_in,
                              void* d_out, int out_size) {
    int* bar = nullptr;
    cudaGetSymbolAddress((void**)&bar, g_bar);

    const float* x   = (const float*)d_in[0];
    const int*   ei  = (const int*)  d_in[1];
    const float* W0  = (const float*)d_in[2];
    const float* b0  = (const float*)d_in[3];
    const float* W1  = (const float*)d_in[4];
    const float* b1  = (const float*)d_in[5];
    const float* W2  = (const float*)d_in[6];
    const float* b2  = (const float*)d_in[7];
    const float* p1  = (const float*)d_in[8];
    const float* p2  = (const float*)d_in[9];
    const float* Wu0 = (const float*)d_in[10];
    const float* bu0 = (const float*)d_in[11];
    const float* Wu1 = (const float*)d_in[12];
    const float* bu1 = (const float*)d_in[13];
    float* out = (float*)d_out;

    cudaMemsetAsync(bar, 0, 64 * sizeof(int), 0);
    mega<<<GRID, TPB>>>(x, ei, W0, b0, W1, b1, W2, b2, p1, p2,
                        Wu0, bu0, Wu1, bu1, out);
}